// round 1
// baseline (speedup 1.0000x reference)
#include <cuda_runtime.h>
#include <cuda_bf16.h>
#include <cstdint>

// Problem constants (from reference):
//   R_MAX=32, S_MAX=2 -> C_R = 66, C_S = 6, DIM_PAIR = 128
//   W rows: [0,66) = W_si, [66,132) = W_ti, 132 = w_ent, [133,139) = W_sym
#define DIM 128

__global__ __launch_bounds__(1024, 2)
void rpe_kernel(const int* __restrict__ seq_index,
                const int* __restrict__ seq_color,
                const int* __restrict__ seq_sym,
                const int* __restrict__ seq_entity,
                const int* __restrict__ token_index,
                const float* __restrict__ W,
                float* __restrict__ out,
                int L)
{
    // Shared tables:
    //   T1[d][k]   = W_si[d][k] + W_ti[65][k]      (66 rows) — covers the d_ti==65 fast path
    //   Wsym[d][k] = W_sym[d][k] + (d!=5)*w_ent[k] (6 rows)  — w_ent folded (bij_entity <=> d_sym!=5)
    __shared__ float sT1[66 * DIM];
    __shared__ float sSym[6 * DIM];

    const int i   = blockIdx.x;
    const int tid = threadIdx.x;

    // ---- build tables (once per block) ----
    for (int idx = tid; idx < 66 * DIM; idx += blockDim.x) {
        int k = idx & (DIM - 1);
        sT1[idx] = W[idx] + W[131 * DIM + k];          // W_si[d] + W_ti[65]
    }
    for (int idx = tid; idx < 6 * DIM; idx += blockDim.x) {
        int d = idx >> 7, k = idx & (DIM - 1);
        float v = W[(133 + d) * DIM + k];
        if (d != 5) v += W[132 * DIM + k];             // fold w_ent
        sSym[idx] = v;
    }
    __syncthreads();

    const int lane  = tid & 31;
    const int warp  = tid >> 5;
    const int nwarp = blockDim.x >> 5;

    const int si_i = __ldg(seq_index  + i);
    const int sc_i = __ldg(seq_color  + i);
    const int ss_i = __ldg(seq_sym    + i);
    const int se_i = __ldg(seq_entity + i);
    const int ti_i = __ldg(token_index + i);

    // Register-cached hot rows (75% color-mismatch, 75% entity-mismatch)
    const float4 base = *reinterpret_cast<const float4*>(sT1  + 65 * DIM + lane * 4); // W_si[65]+W_ti[65]
    const float4 sym5 = *reinterpret_cast<const float4*>(sSym + 5 * DIM  + lane * 4); // W_sym[5]
    const float4 hot  = make_float4(base.x + sym5.x, base.y + sym5.y,
                                    base.z + sym5.z, base.w + sym5.w);

    float4* __restrict__ outrow =
        reinterpret_cast<float4*>(out + (size_t)i * (size_t)L * DIM);

    for (int j = warp; j < L; j += nwarp) {
        const int scj = __ldg(seq_color  + j);
        const int sej = __ldg(seq_entity + j);
        const bool bc = (sc_i == scj);
        const bool be = (se_i == sej);

        float4 v;
        if (!bc && !be) {
            v = hot;                                   // ~56% of pairs: zero smem reads
        } else {
            if (bc) {
                const int sij = __ldg(seq_index + j);
                int d = min(max(si_i - sij, -32), 32) + 32;
                v = *reinterpret_cast<const float4*>(sT1 + d * DIM + lane * 4);
                if (si_i == sij) {
                    // very rare (~0.1%): real token-index bin; add W_ti[d_ti]-W_ti[65] from gmem
                    const int tij = __ldg(token_index + j);
                    int dt = min(max(ti_i - tij, -32), 32) + 32;
                    float4 wt  = __ldg(reinterpret_cast<const float4*>(W + (66 + dt) * DIM + lane * 4));
                    float4 w65 = __ldg(reinterpret_cast<const float4*>(W + 131 * DIM       + lane * 4));
                    v.x += wt.x - w65.x; v.y += wt.y - w65.y;
                    v.z += wt.z - w65.z; v.w += wt.w - w65.w;
                }
            } else {
                v = base;
            }
            float4 s;
            if (be) {
                const int ssj = __ldg(seq_sym + j);
                int ds = min(max(ss_i - ssj, -2), 2) + 2;
                s = *reinterpret_cast<const float4*>(sSym + ds * DIM + lane * 4);
            } else {
                s = sym5;
            }
            v.x += s.x; v.y += s.y; v.z += s.z; v.w += s.w;
        }

        // streaming store: output is write-once, never re-read -> don't pollute L2
        __stcs(outrow + (size_t)j * (DIM / 4) + lane, v);
    }
}

extern "C" void kernel_launch(void* const* d_in, const int* in_sizes, int n_in,
                              void* d_out, int out_size)
{
    const int* seq_index   = (const int*)d_in[0];
    const int* seq_color   = (const int*)d_in[1];
    const int* seq_sym     = (const int*)d_in[2];
    const int* seq_entity  = (const int*)d_in[3];
    const int* token_index = (const int*)d_in[4];
    const float* W         = (const float*)d_in[5];
    float* out             = (float*)d_out;

    const int L = in_sizes[0];   // 1024 (B=1)

    rpe_kernel<<<L, 1024>>>(seq_index, seq_color, seq_sym, seq_entity,
                            token_index, W, out, L);
}

// round 2
// speedup vs baseline: 1.0043x; 1.0043x over previous
#include <cuda_runtime.h>
#include <cuda_bf16.h>
#include <cstdint>

// Problem constants (from reference):
//   R_MAX=32, S_MAX=2 -> C_R = 66, C_S = 6, DIM_PAIR = 128
//   W rows: [0,66) = W_si, [66,132) = W_ti, 132 = w_ent, [133,139) = W_sym
#define DIM 128
#define NCTA 296          // 2 CTAs per SM on 148-SM GB300 (152 on GB300; 296 still 2/SM min)

__global__ __launch_bounds__(1024, 2)
void rpe_kernel(const int* __restrict__ seq_index,
                const int* __restrict__ seq_color,
                const int* __restrict__ seq_sym,
                const int* __restrict__ seq_entity,
                const int* __restrict__ token_index,
                const float* __restrict__ W,
                float* __restrict__ out,
                int L)
{
    // Shared tables:
    //   T1[d][k]   = W_si[d][k] + W_ti[65][k]      (66 rows) — covers the d_ti==65 fast path
    //   Wsym[d][k] = W_sym[d][k] + (d!=5)*w_ent[k] (6 rows)  — w_ent folded (bij_entity <=> d_sym!=5)
    __shared__ float sT1[66 * DIM];
    __shared__ float sSym[6 * DIM];

    const int tid = threadIdx.x;

    for (int idx = tid; idx < 66 * DIM; idx += blockDim.x) {
        int k = idx & (DIM - 1);
        sT1[idx] = W[idx] + W[131 * DIM + k];          // W_si[d] + W_ti[65]
    }
    for (int idx = tid; idx < 6 * DIM; idx += blockDim.x) {
        int d = idx >> 7, k = idx & (DIM - 1);
        float v = W[(133 + d) * DIM + k];
        if (d != 5) v += W[132 * DIM + k];             // fold w_ent
        sSym[idx] = v;
    }
    __syncthreads();

    const int lane  = tid & 31;
    const int warp  = tid >> 5;

    // Register-cached hot rows (i-independent):
    const float4 base = *reinterpret_cast<const float4*>(sT1  + 65 * DIM + lane * 4); // W_si[65]+W_ti[65]
    const float4 sym5 = *reinterpret_cast<const float4*>(sSym + 5 * DIM  + lane * 4); // W_sym'[5]
    const float4 hot  = make_float4(base.x + sym5.x, base.y + sym5.y,
                                    base.z + sym5.z, base.w + sym5.w);

    // Persistent warps grid-stride over the flattened pair space: no wave
    // quantization (1024 rows / 296 CTAs previously left the last wave 46% full).
    const long long npairs      = (long long)L * (long long)L;
    const int       total_warps = gridDim.x * (blockDim.x >> 5);
    const int       gwarp       = blockIdx.x * (blockDim.x >> 5) + warp;

    float4* __restrict__ out4 = reinterpret_cast<float4*>(out);

    for (long long p = gwarp; p < npairs; p += total_warps) {
        const int i = (int)(p / L);
        const int j = (int)(p - (long long)i * L);

        const int sc_i = __ldg(seq_color  + i);
        const int se_i = __ldg(seq_entity + i);
        const int scj  = __ldg(seq_color  + j);
        const int sej  = __ldg(seq_entity + j);
        const bool bc = (sc_i == scj);
        const bool be = (se_i == sej);

        float4 v;
        if (!bc && !be) {
            v = hot;                                   // ~56% of pairs: zero table reads
        } else {
            if (bc) {
                const int si_i = __ldg(seq_index + i);
                const int sij  = __ldg(seq_index + j);
                int d = min(max(si_i - sij, -32), 32) + 32;
                v = *reinterpret_cast<const float4*>(sT1 + d * DIM + lane * 4);
                if (si_i == sij) {
                    // very rare (~0.1%): real token-index bin; add W_ti[d_ti]-W_ti[65] from gmem
                    const int ti_i = __ldg(token_index + i);
                    const int tij  = __ldg(token_index + j);
                    int dt = min(max(ti_i - tij, -32), 32) + 32;
                    float4 wt  = __ldg(reinterpret_cast<const float4*>(W + (66 + dt) * DIM + lane * 4));
                    float4 w65 = __ldg(reinterpret_cast<const float4*>(W + 131 * DIM       + lane * 4));
                    v.x += wt.x - w65.x; v.y += wt.y - w65.y;
                    v.z += wt.z - w65.z; v.w += wt.w - w65.w;
                }
            } else {
                v = base;
            }
            float4 s;
            if (be) {
                const int ss_i = __ldg(seq_sym + i);
                const int ssj  = __ldg(seq_sym + j);
                int ds = min(max(ss_i - ssj, -2), 2) + 2;
                s = *reinterpret_cast<const float4*>(sSym + ds * DIM + lane * 4);
            } else {
                s = sym5;
            }
            v.x += s.x; v.y += s.y; v.z += s.z; v.w += s.w;
        }

        // streaming store: output is write-once, never re-read -> don't pollute L2
        __stcs(out4 + p * (DIM / 4) + lane, v);
    }
}

extern "C" void kernel_launch(void* const* d_in, const int* in_sizes, int n_in,
                              void* d_out, int out_size)
{
    const int* seq_index   = (const int*)d_in[0];
    const int* seq_color   = (const int*)d_in[1];
    const int* seq_sym     = (const int*)d_in[2];
    const int* seq_entity  = (const int*)d_in[3];
    const int* token_index = (const int*)d_in[4];
    const float* W         = (const float*)d_in[5];
    float* out             = (float*)d_out;

    const int L = in_sizes[0];   // 1024 (B=1)

    rpe_kernel<<<NCTA, 1024>>>(seq_index, seq_color, seq_sym, seq_entity,
                               token_index, W, out, L);
}